// round 15
// baseline (speedup 1.0000x reference)
#include <cuda_runtime.h>
#include <cuda_bf16.h>

#define H     2048
#define G4    8192          // 4*H gate rows
#define V     28
#define T     512
#define NCTA  148
#define CPB   14            // h-indices per CTA
#define ROWS  56            // gate rows per CTA
#define SMEM_ROWS 54        // rows resident in SMEM; rows 54,55 stream from L2
#define WMAT  16777216      // G4*H elements per matrix
#define KMAGIC 8421376.0f   // 2^23 + 32768 (biased-u16 float offset)
#define EPOCH 2048u         // stamp-space advance per launch (>= 1026 used)

// dynamic smem layout (u32 units)
#define OFF_W     0
#define OFF_H     (SMEM_ROWS * 1024)            // 55296
#define OFF_PART  (OFF_H + 2048)                // 57344  : 56 rows x 4 slices
#define SMEM_U32  (OFF_PART + ROWS * 4)         // 57568
#define SMEM_BYTES (SMEM_U32 * 4)               // 230272 (<= 227KB opt-in)

// ---- device scratch (no allocations allowed) ----
__device__ float          g_table[2u * V * G4]; // [enc/dec][vocab][4H] gate table
__device__ unsigned short g_Wq[2][WMAT];        // biased-u16 quantized Whh
__device__ float          g_wscale[2][G4];      // per-row dequant scales
// hidden state, 4-deep ring, SELF-FLAGGED: low32 = value bits, high32 = stamp.
__device__ __align__(16) unsigned long long g_hd[4][H];
__device__ unsigned       g_base;               // stamp epoch (+=EPOCH per launch)

__device__ __forceinline__ float warpsum(float v) {
#pragma unroll
    for (int o = 16; o; o >>= 1) v += __shfl_xor_sync(0xffffffffu, v, o);
    return v;
}
__device__ __forceinline__ float sigm(float x) { return 1.0f / (1.0f + expf(-x)); }

// Publish one (value,stamp) word: strong release store.
__device__ __forceinline__ void publish_h(unsigned long long* dst, float v,
                                          unsigned stamp) {
    unsigned long long pk =
        ((unsigned long long)stamp << 32) | (unsigned long long)__float_as_uint(v);
    asm volatile("st.release.gpu.global.b64 [%0], %1;"
                 :: "l"(dst), "l"(pk) : "memory");
}

// Poll: cheap weak spin on the stamp words, then one-shot strong acquire
// finals (single-copy-atomic value+stamp, ordered). Proven in R13/R14.
__device__ __forceinline__ float2 poll_h2(const unsigned long long* src,
                                          unsigned want) {
    const unsigned* st = reinterpret_cast<const unsigned*>(src);
    unsigned s0, s1;
    do {
        asm volatile("ld.global.cg.u32 %0, [%1];" : "=r"(s0) : "l"(st + 1));
        asm volatile("ld.global.cg.u32 %0, [%1];" : "=r"(s1) : "l"(st + 3));
    } while (s0 != want || s1 != want);
    unsigned long long v0, v1;
    do {
        asm volatile("ld.acquire.gpu.global.b64 %0, [%1];"
                     : "=l"(v0) : "l"(src) : "memory");
    } while ((unsigned)(v0 >> 32) != want);
    do {
        asm volatile("ld.acquire.gpu.global.b64 %0, [%1];"
                     : "=l"(v1) : "l"(src + 1) : "memory");
    } while ((unsigned)(v1 >> 32) != want);
    return make_float2(__uint_as_float((unsigned)v0),
                       __uint_as_float((unsigned)v1));
}

// biased-u16 pair -> packed f32x2 (value = 2^23 + biased) via 2 PRMT + pair.
__device__ __forceinline__ unsigned long long pk2(unsigned u) {
    unsigned long long r;
    asm("{\n\t.reg .b32 lo, hi;\n\t"
        "prmt.b32 lo, %1, %2, 0x7410;\n\t"
        "prmt.b32 hi, %1, %2, 0x7432;\n\t"
        "mov.b64 %0, {lo, hi};\n\t}"
        : "=l"(r) : "r"(u), "r"(0x4B000000u));
    return r;
}
// packed dual-FMA (Blackwell FFMA2): a += w * h elementwise on f32x2
__device__ __forceinline__ void fma2(unsigned long long& a,
                                     unsigned long long wv,
                                     unsigned long long hv) {
    asm("fma.rn.f32x2 %0, %1, %2, %0;" : "+l"(a) : "l"(wv), "l"(hv));
}
__device__ __forceinline__ unsigned long long pkf(float lo, float hi) {
    unsigned long long r;
    asm("mov.b64 %0, {%1, %2};" : "=l"(r) : "f"(lo), "f"(hi));
    return r;
}
__device__ __forceinline__ float unpk_sum(unsigned long long a,
                                          unsigned long long b) {
    float x0, y0, x1, y1;
    asm("mov.b64 {%0, %1}, %2;" : "=f"(x0), "=f"(y0) : "l"(a));
    asm("mov.b64 {%0, %1}, %2;" : "=f"(x1), "=f"(y1) : "l"(b));
    return (x0 + y0) + (x1 + y1);
}

// One 512-elem row-slice dot: 4 uint2 (16 elems/lane) against hp[0..7].
#define ROW_DOT2(w0, w1, w2, w3, OUTVAR)                                  \
    float OUTVAR;                                                         \
    {                                                                     \
        unsigned long long a0 = 0ull, a1 = 0ull;                          \
        fma2(a0, pk2(w0.x), hp[0]); fma2(a1, pk2(w0.y), hp[1]);           \
        fma2(a0, pk2(w1.x), hp[2]); fma2(a1, pk2(w1.y), hp[3]);           \
        fma2(a0, pk2(w2.x), hp[4]); fma2(a1, pk2(w2.y), hp[5]);           \
        fma2(a0, pk2(w3.x), hp[6]); fma2(a1, pk2(w3.y), hp[7]);           \
        OUTVAR = fmaf(-KMAGIC, hsum, unpk_sum(a0, a1));                   \
    }

// ---------------------------------------------------------------------------
// Quantize Whh rows to biased uint16 with per-row fp32 scale.
// ---------------------------------------------------------------------------
__global__ __launch_bounds__(256) void k_quant(
    const float* __restrict__ encW, const float* __restrict__ decW)
{
    __shared__ float s_max[8];
    const int r     = blockIdx.x;       // 0..16383
    const int which = r >> 13;
    const int row   = r & (G4 - 1);
    const int tid = threadIdx.x, lane = tid & 31, w = tid >> 5;

    const float4* W4 = reinterpret_cast<const float4*>(
        (which ? decW : encW) + (size_t)row * H);

    float4 v0 = __ldg(&W4[tid]);
    float4 v1 = __ldg(&W4[tid + 256]);

    float m = fmaxf(fmaxf(fabsf(v0.x), fabsf(v0.y)), fmaxf(fabsf(v0.z), fabsf(v0.w)));
    m = fmaxf(m, fmaxf(fmaxf(fabsf(v1.x), fabsf(v1.y)), fmaxf(fabsf(v1.z), fabsf(v1.w))));
#pragma unroll
    for (int o = 16; o; o >>= 1) m = fmaxf(m, __shfl_xor_sync(0xffffffffu, m, o));
    if (lane == 0) s_max[w] = m;
    __syncthreads();
    if (tid == 0) {
        float mm = s_max[0];
#pragma unroll
        for (int i = 1; i < 8; i++) mm = fmaxf(mm, s_max[i]);
        s_max[0] = mm;
        g_wscale[which][row] = mm * (1.0f / 32766.0f);
    }
    __syncthreads();
    const float mv  = s_max[0];
    const float inv = (mv > 0.0f) ? (32766.0f / mv) : 0.0f;

    ushort4* Q4 = reinterpret_cast<ushort4*>(&g_Wq[which][(size_t)row * H]);
    ushort4 q;
    q.x = (unsigned short)(__float2int_rn(v0.x * inv) + 32768);
    q.y = (unsigned short)(__float2int_rn(v0.y * inv) + 32768);
    q.z = (unsigned short)(__float2int_rn(v0.z * inv) + 32768);
    q.w = (unsigned short)(__float2int_rn(v0.w * inv) + 32768);
    Q4[tid] = q;
    q.x = (unsigned short)(__float2int_rn(v1.x * inv) + 32768);
    q.y = (unsigned short)(__float2int_rn(v1.y * inv) + 32768);
    q.z = (unsigned short)(__float2int_rn(v1.z * inv) + 32768);
    q.w = (unsigned short)(__float2int_rn(v1.w * inv) + 32768);
    Q4[tid + 256] = q;
}

// ---------------------------------------------------------------------------
// Precompute per-vocab gate tables; block 0 also advances the stamp epoch and
// publishes S(0)=0 into ring buffer 0 with the new base (graph-replay safe).
// ---------------------------------------------------------------------------
__global__ __launch_bounds__(256) void k_pre(
    const float* __restrict__ enc_emb, const float* __restrict__ enc_Wih,
    const float* __restrict__ enc_bih, const float* __restrict__ enc_bhh,
    const float* __restrict__ dec_emb, const float* __restrict__ dec_Wih,
    const float* __restrict__ dec_bih, const float* __restrict__ dec_bhh)
{
    __shared__ __align__(16) float s_emb[V][256];
    __shared__ unsigned s_base;
    const int tid = threadIdx.x, lane = tid & 31, warp = tid >> 5;

    if (blockIdx.x == 0) {
        if (tid == 0) {
            unsigned nb = g_base + EPOCH;
            g_base = nb;
            s_base = nb;
        }
        __syncthreads();
        const unsigned nb = s_base;
        for (int j = tid; j < H; j += 256)
            publish_h(&g_hd[0][j], 0.0f, nb);
    }

    const int   which = (blockIdx.x >= 1024) ? 1 : 0;
    const float* emb = which ? dec_emb : enc_emb;
    const float* Wih = which ? dec_Wih : enc_Wih;
    const float* bih = which ? dec_bih : enc_bih;
    const float* bhh = which ? dec_bhh : enc_bhh;
    const int row = (blockIdx.x & 1023) * 8 + warp;   // 0..8191

    float acc[V];
#pragma unroll
    for (int v = 0; v < V; v++) acc[v] = 0.0f;

    for (int kt = 0; kt < 8; kt++) {
        const int k0 = kt * 256;
        __syncthreads();
        for (int idx = tid; idx < V * 256; idx += 256) {
            int v = idx >> 8, kk = idx & 255;
            s_emb[v][kk] = __ldg(&emb[v * H + k0 + kk]);
        }
        __syncthreads();
        const float4* Wr = reinterpret_cast<const float4*>(Wih + (size_t)row * H + k0);
#pragma unroll
        for (int it = 0; it < 2; it++) {
            const int kl = it * 32 + lane;
            float4 w4 = __ldg(&Wr[kl]);
#pragma unroll
            for (int v = 0; v < V; v++) {
                float4 e = reinterpret_cast<const float4*>(s_emb[v])[kl];
                acc[v] += w4.x * e.x + w4.y * e.y + w4.z * e.z + w4.w * e.w;
            }
        }
    }

    float bias = 0.0f;
#pragma unroll
    for (int v = 0; v < V; v++) {
        float s = warpsum(acc[v]);
        if (lane == 0) {
            if (v == 0) bias = __ldg(&bih[row]) + __ldg(&bhh[row]);
            g_table[(size_t)which * V * G4 + (size_t)v * G4 + row] = s + bias;
        }
    }
}

// ---------------------------------------------------------------------------
// Persistent LSTM kernel. 148 CTAs x 1024 threads. Sync identical to R13/14.
// NEW: 54 weight rows SMEM-resident (rows 54,55 streamed by warp-groups 6,7),
// packed f32x2 FMA (FFMA2) in the row dots.
// Row map: group g handles lr = g+8k; smem slot sidx = g*7+k (g<6) or
// 42+(g-6)*6+k (g>=6, k<6). Streamed: lr = 48+g for g in {6,7}.
// ---------------------------------------------------------------------------
__global__ __launch_bounds__(1024, 1) void k_main(
    const int*   __restrict__ x,      const int*   __restrict__ target,
    const float* __restrict__ eps,
    const float* __restrict__ mu_W,    const float* __restrict__ mu_b,
    const float* __restrict__ lv_W,    const float* __restrict__ lv_b,
    float* __restrict__ out)
{
    extern __shared__ __align__(16) unsigned s_dyn[];
    unsigned* s_w     = s_dyn + OFF_W;               // [54][1024] u32 (2 u16)
    float*    s_h     = (float*)(s_dyn + OFF_H);     // [2048]
    float*    s_part  = (float*)(s_dyn + OFF_PART);  // [56][4]

    const int tid = threadIdx.x, lane = tid & 31, w = tid >> 5;
    const int g = w >> 2;        // row-group 0..7
    const int q = w & 3;         // k-slice 0..3
    const int j0 = blockIdx.x * CPB;
    int nloc = H - j0;
    if (nloc > CPB) nloc = CPB;
    if (nloc < 0)  nloc = 0;
    const int nrows = nloc * 4;
    const bool full = (nloc == CPB);

    float cacc = 0.0f;                       // LSTM cell state (owner threads)
    const unsigned base = g_base;            // set by k_pre this launch

    for (int phase = 0; phase < 2; phase++) {
        const unsigned short* Wq = g_Wq[phase];
        const float* wsc   = g_wscale[phase];
        const float* table = g_table + (size_t)phase * V * G4;

        // ---- load the 54 SMEM-resident weight rows for this phase ----
        __syncthreads();
        {
            const unsigned* Wq32 = reinterpret_cast<const unsigned*>(Wq);
            for (int g2 = 0; g2 < 8; g2++) {
                const int kc = (g2 < 6) ? 7 : 6;
                for (int k = 0; k < kc; k++) {
                    const int lr = g2 + 8 * k;
                    if (lr < nrows) {
                        const int sidx = (g2 < 6) ? (g2 * 7 + k)
                                                  : (42 + (g2 - 6) * 6 + k);
                        const int row = (lr & 3) * H + j0 + (lr >> 2);
                        s_w[sidx * 1024 + tid] =
                            __ldg(&Wq32[(size_t)row * 1024 + tid]);
                    }
                }
            }
        }
        __syncthreads();

        float wscR[4];                        // owner dequant scales (static)
        if (tid < nloc) {
#pragma unroll
            for (int ga = 0; ga < 4; ga++)
                wscR[ga] = __ldg(&wsc[ga * H + j0 + tid]);
        }

        for (int t = 0; t < T; t++) {
            const int sread = (phase == 0) ? t : (513 + t);
            const int rbuf  = sread & 3;
            const int wbuf  = (sread + 1) & 3;
            const unsigned want = base + (unsigned)sread;

            // owner: issue tok load before the poll (hidden by it)
            int tok = 0;
            if (tid < nloc)
                tok = (phase == 0) ? __ldg(&x[t])
                                   : (t == 0 ? 0 : __ldg(&target[t - 1]));

            // stream prefetch: groups 6,7 fetch row 48+g from L2
            const int lrs = 48 + g;
            const bool strm = (g >= 6) && (lrs < nrows);
            uint2 pfr[4];
            if (strm) {
                const int row = (lrs & 3) * H + j0 + (lrs >> 2);
                const uint2* gw = reinterpret_cast<const uint2*>(
                    Wq + (size_t)row * H) + q * 128 + lane;
#pragma unroll
                for (int c = 0; c < 4; c++) pfr[c] = __ldg(&gw[c * 32]);
            }

            // self-flagged h: poll this thread's two elements, drop into smem
            reinterpret_cast<float2*>(s_h)[tid] =
                poll_h2(&g_hd[rbuf][2 * tid], want);
            __syncthreads();

            // owner: prefetch the 4 table entries (consumed after the dot)
            float tpre[4];
            if (tid < nloc) {
#pragma unroll
                for (int ga = 0; ga < 4; ga++)
                    tpre[ga] = __ldg(&table[(size_t)tok * G4 + ga * H + j0 + tid]);
            }

            // per-warp h-slice, packed f32x2: k = q*512 + c*128 + lane*4
            const float4* sh4 = reinterpret_cast<const float4*>(s_h);
            unsigned long long hp[8];
            float hsum = 0.0f;
#pragma unroll
            for (int c = 0; c < 4; c++) {
                float4 hv = sh4[q * 128 + c * 32 + lane];
                hp[2 * c]     = pkf(hv.x, hv.y);
                hp[2 * c + 1] = pkf(hv.z, hv.w);
                hsum += (hv.x + hv.y) + (hv.z + hv.w);
            }

            if (full) {
                if (g < 6) {
                    const uint2* wbase = reinterpret_cast<const uint2*>(s_w) +
                                         (size_t)(g * 7) * 512 + q * 128 + lane;
#pragma unroll
                    for (int k = 0; k < 7; k++) {
                        const uint2* wp = wbase + (size_t)k * 512;
                        uint2 w0 = wp[0], w1 = wp[32], w2 = wp[64], w3 = wp[96];
                        ROW_DOT2(w0, w1, w2, w3, accr)
                        float s = warpsum(accr);
                        if (lane == 0) s_part[(g + 8 * k) * 4 + q] = s;
                    }
                } else {
                    const uint2* wbase = reinterpret_cast<const uint2*>(s_w) +
                                         (size_t)(42 + (g - 6) * 6) * 512 +
                                         q * 128 + lane;
#pragma unroll
                    for (int k = 0; k < 6; k++) {
                        const uint2* wp = wbase + (size_t)k * 512;
                        uint2 w0 = wp[0], w1 = wp[32], w2 = wp[64], w3 = wp[96];
                        ROW_DOT2(w0, w1, w2, w3, accr)
                        float s = warpsum(accr);
                        if (lane == 0) s_part[(g + 8 * k) * 4 + q] = s;
                    }
                    ROW_DOT2(pfr[0], pfr[1], pfr[2], pfr[3], accr)
                    float s = warpsum(accr);
                    if (lane == 0) s_part[(48 + g) * 4 + q] = s;
                }
            } else if (nloc > 0) {
                // ---- slow path (tail CTA): guarded loops, smem rows only ----
                const int kc = (g < 6) ? 7 : 6;
                for (int k = 0; k < kc; k++) {
                    const int lr = g + 8 * k;
                    if (lr < nrows) {
                        const int sidx = (g < 6) ? (g * 7 + k)
                                                 : (42 + (g - 6) * 6 + k);
                        const uint2* wp = reinterpret_cast<const uint2*>(s_w) +
                                          (size_t)sidx * 512 + q * 128 + lane;
                        uint2 w0 = wp[0], w1 = wp[32], w2 = wp[64], w3 = wp[96];
                        ROW_DOT2(w0, w1, w2, w3, accr)
                        float s = warpsum(accr);
                        if (lane == 0) s_part[lr * 4 + q] = s;
                    }
                }
                if (strm) {
                    ROW_DOT2(pfr[0], pfr[1], pfr[2], pfr[3], accr)
                    float s = warpsum(accr);
                    if (lane == 0) s_part[lrs * 4 + q] = s;
                }
            }
            __syncthreads();

            // fused combine + dequant + table + cell update (owner threads)
            if (tid < nloc) {
                const float4* sp4 = reinterpret_cast<const float4*>(s_part);
                float4 p0 = sp4[tid * 4 + 0];
                float4 p1 = sp4[tid * 4 + 1];
                float4 p2 = sp4[tid * 4 + 2];
                float4 p3 = sp4[tid * 4 + 3];
                float g0 = ((p0.x + p0.y) + (p0.z + p0.w)) * wscR[0] + tpre[0];
                float g1 = ((p1.x + p1.y) + (p1.z + p1.w)) * wscR[1] + tpre[1];
                float g2 = ((p2.x + p2.y) + (p2.z + p2.w)) * wscR[2] + tpre[2];
                float g3 = ((p3.x + p3.y) + (p3.z + p3.w)) * wscR[3] + tpre[3];
                float c = sigm(g1) * cacc + sigm(g0) * tanhf(g2);
                cacc = c;
                float h = sigm(g3) * tanhf(c);
                publish_h(&g_hd[wbuf][j0 + tid], h, want + 1u);
                if (phase)
                    out[512 + (size_t)t * H + j0 + tid] = h;
            }
            // no grid barrier
        }

        if (phase == 0) {
            // VAE heads: s=512. read h_enc (buf 0, stamp base+512),
            // write z -> buf 1, stamp base+513.
            const unsigned want = base + 512u;
            reinterpret_cast<float2*>(s_h)[tid] =
                poll_h2(&g_hd[0][2 * tid], want);
            __syncthreads();
            const float4* sh4 = reinterpret_cast<const float4*>(s_h);
            if (w < nloc * 2) {
                const int l = w >> 1, m = w & 1;
                const float* Wm = m ? lv_W : mu_W;
                const int row = j0 + l;
                const float4* W4 = reinterpret_cast<const float4*>(Wm) +
                                   (size_t)row * (H / 4);
                float s = 0.0f;
#pragma unroll 8
                for (int i = lane; i < H / 4; i += 32) {
                    float4 a = __ldg(&W4[i]);
                    float4 b = sh4[i];
                    s += a.x * b.x + a.y * b.y + a.z * b.z + a.w * b.w;
                }
                s = warpsum(s);
                if (lane == 0)
                    s_part[w] = s + __ldg(&(m ? lv_b : mu_b)[row]);
            }
            __syncthreads();
            if (tid < nloc) {
                const int j = j0 + tid;
                const float mu = s_part[tid * 2 + 0];
                const float lv = s_part[tid * 2 + 1];
                out[512 + (size_t)T * H + j]     = mu;
                out[512 + (size_t)T * H + H + j] = lv;
                float z = mu + __ldg(&eps[j]) * expf(0.5f * lv);
                publish_h(&g_hd[1][j], z, want + 1u);
            }
        }
    }
}

// ---------------------------------------------------------------------------
// Argmax over hidden dim of each decoder output row (first-index tie-break).
// ---------------------------------------------------------------------------
__global__ __launch_bounds__(256) void k_argmax(float* __restrict__ out)
{
    __shared__ float sv[256];
    __shared__ int   si[256];
    const int t = blockIdx.x;
    const float* row = out + 512 + (size_t)t * H;
    float best = -3.402823466e+38f;
    int   bi = 0;
    for (int j = threadIdx.x; j < H; j += 256) {
        float v = row[j];
        if (v > best) { best = v; bi = j; }
    }
    sv[threadIdx.x] = best;
    si[threadIdx.x] = bi;
    __syncthreads();
    for (int s = 128; s; s >>= 1) {
        if (threadIdx.x < s) {
            float ov = sv[threadIdx.x + s];
            int   oi = si[threadIdx.x + s];
            if (ov > sv[threadIdx.x] ||
                (ov == sv[threadIdx.x] && oi < si[threadIdx.x])) {
                sv[threadIdx.x] = ov;
                si[threadIdx.x] = oi;
            }
        }
        __syncthreads();
    }
    if (threadIdx.x == 0) out[t] = (float)si[0];
}

// ---------------------------------------------------------------------------
extern "C" void kernel_launch(void* const* d_in, const int* in_sizes, int n_in,
                              void* d_out, int out_size)
{
    const int*   x       = (const int*)  d_in[0];
    const int*   target  = (const int*)  d_in[1];
    const float* eps     = (const float*)d_in[2];
    const float* enc_emb = (const float*)d_in[3];
    const float* enc_Wih = (const float*)d_in[4];
    const float* enc_Whh = (const float*)d_in[5];
    const float* enc_bih = (const float*)d_in[6];
    const float* enc_bhh = (const float*)d_in[7];
    const float* mu_W    = (const float*)d_in[8];
    const float* mu_b    = (const float*)d_in[9];
    const float* lv_W    = (const float*)d_in[10];
    const float* lv_b    = (const float*)d_in[11];
    const float* dec_emb = (const float*)d_in[12];
    const float* dec_Wih = (const float*)d_in[13];
    const float* dec_Whh = (const float*)d_in[14];
    const float* dec_bih = (const float*)d_in[15];
    const float* dec_bhh = (const float*)d_in[16];
    float* out = (float*)d_out;

    cudaFuncSetAttribute(k_main, cudaFuncAttributeMaxDynamicSharedMemorySize,
                         SMEM_BYTES);

    k_pre<<<2048, 256>>>(enc_emb, enc_Wih, enc_bih, enc_bhh,
                         dec_emb, dec_Wih, dec_bih, dec_bhh);
    k_quant<<<2 * G4, 256>>>(enc_Whh, dec_Whh);
    k_main<<<NCTA, 1024, SMEM_BYTES>>>(x, target, eps,
                                       mu_W, mu_b, lv_W, lv_b, out);
    k_argmax<<<512, 256>>>(out);
}

// round 16
// speedup vs baseline: 1.0664x; 1.0664x over previous
#include <cuda_runtime.h>
#include <cuda_bf16.h>

#define H     2048
#define G4    8192          // 4*H gate rows
#define V     28
#define T     512
#define NCTA  148
#define CPB   14            // h-indices per CTA
#define ROWS  56            // gate rows per CTA
#define SMEM_ROWS 54        // rows resident in SMEM; rows 54,55 in registers
#define WMAT  16777216      // G4*H elements per matrix
#define KMAGIC 8421376.0f   // 2^23 + 32768 (biased-u16 float offset)
#define EPOCH 2048u         // stamp-space advance per launch (>= 1026 used)

// dynamic smem layout (u32 units)
#define OFF_W     0
#define OFF_H     (SMEM_ROWS * 1024)            // 55296
#define OFF_PART  (OFF_H + 2048)                // 57344  : 56 rows x 4 slices
#define SMEM_U32  (OFF_PART + ROWS * 4)         // 57568
#define SMEM_BYTES (SMEM_U32 * 4)               // 230272 (<= 227KB opt-in)

// ---- device scratch (no allocations allowed) ----
__device__ float          g_table[2u * V * G4]; // [enc/dec][vocab][4H] gate table
__device__ unsigned short g_Wq[2][WMAT];        // biased-u16 quantized Whh
__device__ float          g_wscale[2][G4];      // per-row dequant scales
// hidden state, 4-deep ring, SELF-FLAGGED: low32 = value bits, high32 = stamp.
__device__ __align__(16) unsigned long long g_hd[4][H];
__device__ unsigned       g_base;               // stamp epoch (+=EPOCH per launch)

__device__ __forceinline__ float warpsum(float v) {
#pragma unroll
    for (int o = 16; o; o >>= 1) v += __shfl_xor_sync(0xffffffffu, v, o);
    return v;
}
__device__ __forceinline__ float sigm(float x) { return 1.0f / (1.0f + expf(-x)); }

// Publish one (value,stamp) word: strong release store.
__device__ __forceinline__ void publish_h(unsigned long long* dst, float v,
                                          unsigned stamp) {
    unsigned long long pk =
        ((unsigned long long)stamp << 32) | (unsigned long long)__float_as_uint(v);
    asm volatile("st.release.gpu.global.b64 [%0], %1;"
                 :: "l"(dst), "l"(pk) : "memory");
}

// Poll: dual acquire-load spin (both loads independent -> in flight together).
// Morally-strong 8B accesses (proven R13); exact-match stamps.
__device__ __forceinline__ float2 poll_h2(const unsigned long long* src,
                                          unsigned want) {
    unsigned long long v0, v1;
    for (;;) {
        asm volatile("ld.acquire.gpu.global.b64 %0, [%1];"
                     : "=l"(v0) : "l"(src) : "memory");
        asm volatile("ld.acquire.gpu.global.b64 %0, [%1];"
                     : "=l"(v1) : "l"(src + 1) : "memory");
        if ((unsigned)(v0 >> 32) == want && (unsigned)(v1 >> 32) == want) break;
    }
    return make_float2(__uint_as_float((unsigned)v0),
                       __uint_as_float((unsigned)v1));
}

// biased-u16 pair -> packed f32x2 (value = 2^23 + biased) via 2 PRMT + pair.
__device__ __forceinline__ unsigned long long pk2(unsigned u) {
    unsigned long long r;
    asm("{\n\t.reg .b32 lo, hi;\n\t"
        "prmt.b32 lo, %1, %2, 0x7410;\n\t"
        "prmt.b32 hi, %1, %2, 0x7432;\n\t"
        "mov.b64 %0, {lo, hi};\n\t}"
        : "=l"(r) : "r"(u), "r"(0x4B000000u));
    return r;
}
__device__ __forceinline__ void fma2(unsigned long long& a,
                                     unsigned long long wv,
                                     unsigned long long hv) {
    asm("fma.rn.f32x2 %0, %1, %2, %0;" : "+l"(a) : "l"(wv), "l"(hv));
}
__device__ __forceinline__ unsigned long long pkf(float lo, float hi) {
    unsigned long long r;
    asm("mov.b64 %0, {%1, %2};" : "=l"(r) : "f"(lo), "f"(hi));
    return r;
}
__device__ __forceinline__ float unpk_sum(unsigned long long a,
                                          unsigned long long b) {
    float x0, y0, x1, y1;
    asm("mov.b64 {%0, %1}, %2;" : "=f"(x0), "=f"(y0) : "l"(a));
    asm("mov.b64 {%0, %1}, %2;" : "=f"(x1), "=f"(y1) : "l"(b));
    return (x0 + y0) + (x1 + y1);
}

#define ROW_DOT2(w0, w1, w2, w3, OUTVAR)                                  \
    float OUTVAR;                                                         \
    {                                                                     \
        unsigned long long a0 = 0ull, a1 = 0ull;                          \
        fma2(a0, pk2(w0.x), hp[0]); fma2(a1, pk2(w0.y), hp[1]);           \
        fma2(a0, pk2(w1.x), hp[2]); fma2(a1, pk2(w1.y), hp[3]);           \
        fma2(a0, pk2(w2.x), hp[4]); fma2(a1, pk2(w2.y), hp[5]);           \
        fma2(a0, pk2(w3.x), hp[6]); fma2(a1, pk2(w3.y), hp[7]);           \
        OUTVAR = fmaf(-KMAGIC, hsum, unpk_sum(a0, a1));                   \
    }

// ---------------------------------------------------------------------------
// Quantize Whh rows to biased uint16 with per-row fp32 scale.
// ---------------------------------------------------------------------------
__global__ __launch_bounds__(256) void k_quant(
    const float* __restrict__ encW, const float* __restrict__ decW)
{
    __shared__ float s_max[8];
    const int r     = blockIdx.x;       // 0..16383
    const int which = r >> 13;
    const int row   = r & (G4 - 1);
    const int tid = threadIdx.x, lane = tid & 31, w = tid >> 5;

    const float4* W4 = reinterpret_cast<const float4*>(
        (which ? decW : encW) + (size_t)row * H);

    float4 v0 = __ldg(&W4[tid]);
    float4 v1 = __ldg(&W4[tid + 256]);

    float m = fmaxf(fmaxf(fabsf(v0.x), fabsf(v0.y)), fmaxf(fabsf(v0.z), fabsf(v0.w)));
    m = fmaxf(m, fmaxf(fmaxf(fabsf(v1.x), fabsf(v1.y)), fmaxf(fabsf(v1.z), fabsf(v1.w))));
#pragma unroll
    for (int o = 16; o; o >>= 1) m = fmaxf(m, __shfl_xor_sync(0xffffffffu, m, o));
    if (lane == 0) s_max[w] = m;
    __syncthreads();
    if (tid == 0) {
        float mm = s_max[0];
#pragma unroll
        for (int i = 1; i < 8; i++) mm = fmaxf(mm, s_max[i]);
        s_max[0] = mm;
        g_wscale[which][row] = mm * (1.0f / 32766.0f);
    }
    __syncthreads();
    const float mv  = s_max[0];
    const float inv = (mv > 0.0f) ? (32766.0f / mv) : 0.0f;

    ushort4* Q4 = reinterpret_cast<ushort4*>(&g_Wq[which][(size_t)row * H]);
    ushort4 q;
    q.x = (unsigned short)(__float2int_rn(v0.x * inv) + 32768);
    q.y = (unsigned short)(__float2int_rn(v0.y * inv) + 32768);
    q.z = (unsigned short)(__float2int_rn(v0.z * inv) + 32768);
    q.w = (unsigned short)(__float2int_rn(v0.w * inv) + 32768);
    Q4[tid] = q;
    q.x = (unsigned short)(__float2int_rn(v1.x * inv) + 32768);
    q.y = (unsigned short)(__float2int_rn(v1.y * inv) + 32768);
    q.z = (unsigned short)(__float2int_rn(v1.z * inv) + 32768);
    q.w = (unsigned short)(__float2int_rn(v1.w * inv) + 32768);
    Q4[tid + 256] = q;
}

// ---------------------------------------------------------------------------
// Precompute per-vocab gate tables. 2 rows per warp (halves LDS per FMA).
// grid 1024 x 256: block handles 16 rows of one matrix.
// Block 0 also advances the stamp epoch and publishes S(0)=0.
// ---------------------------------------------------------------------------
__global__ __launch_bounds__(256) void k_pre(
    const float* __restrict__ enc_emb, const float* __restrict__ enc_Wih,
    const float* __restrict__ enc_bih, const float* __restrict__ enc_bhh,
    const float* __restrict__ dec_emb, const float* __restrict__ dec_Wih,
    const float* __restrict__ dec_bih, const float* __restrict__ dec_bhh)
{
    __shared__ __align__(16) float s_emb[V][256];
    __shared__ unsigned s_base;
    const int tid = threadIdx.x, lane = tid & 31, warp = tid >> 5;

    if (blockIdx.x == 0) {
        if (tid == 0) {
            unsigned nb = g_base + EPOCH;
            g_base = nb;
            s_base = nb;
        }
        __syncthreads();
        const unsigned nb = s_base;
        for (int j = tid; j < H; j += 256)
            publish_h(&g_hd[0][j], 0.0f, nb);
    }

    const int   which = (blockIdx.x >= 512) ? 1 : 0;
    const float* emb = which ? dec_emb : enc_emb;
    const float* Wih = which ? dec_Wih : enc_Wih;
    const float* bih = which ? dec_bih : enc_bih;
    const float* bhh = which ? dec_bhh : enc_bhh;
    const int row0 = (blockIdx.x & 511) * 16 + warp * 2;   // even row

    float acc0[V], acc1[V];
#pragma unroll
    for (int v = 0; v < V; v++) { acc0[v] = 0.0f; acc1[v] = 0.0f; }

    for (int kt = 0; kt < 8; kt++) {
        const int k0 = kt * 256;
        __syncthreads();
        for (int idx = tid; idx < V * 256; idx += 256) {
            int v = idx >> 8, kk = idx & 255;
            s_emb[v][kk] = __ldg(&emb[v * H + k0 + kk]);
        }
        __syncthreads();
        const float4* W0 = reinterpret_cast<const float4*>(
            Wih + (size_t)row0 * H + k0);
        const float4* W1 = reinterpret_cast<const float4*>(
            Wih + (size_t)(row0 + 1) * H + k0);
#pragma unroll
        for (int it = 0; it < 2; it++) {
            const int kl = it * 32 + lane;
            float4 a0 = __ldg(&W0[kl]);
            float4 a1 = __ldg(&W1[kl]);
#pragma unroll
            for (int v = 0; v < V; v++) {
                float4 e = reinterpret_cast<const float4*>(s_emb[v])[kl];
                acc0[v] += a0.x * e.x + a0.y * e.y + a0.z * e.z + a0.w * e.w;
                acc1[v] += a1.x * e.x + a1.y * e.y + a1.z * e.z + a1.w * e.w;
            }
        }
    }

    float b0 = 0.0f, b1 = 0.0f;
#pragma unroll
    for (int v = 0; v < V; v++) {
        float s0 = warpsum(acc0[v]);
        float s1 = warpsum(acc1[v]);
        if (lane == 0) {
            if (v == 0) {
                b0 = __ldg(&bih[row0]) + __ldg(&bhh[row0]);
                b1 = __ldg(&bih[row0 + 1]) + __ldg(&bhh[row0 + 1]);
            }
            g_table[(size_t)which * V * G4 + (size_t)v * G4 + row0]     = s0 + b0;
            g_table[(size_t)which * V * G4 + (size_t)v * G4 + row0 + 1] = s1 + b1;
        }
    }
}

// ---------------------------------------------------------------------------
// Persistent LSTM kernel. 148 CTAs x 1024 threads. Sync = self-flagged h
// (R13 semantics). All 56 rows now effectively resident: 54 in SMEM, rows
// 54/55 in registers (groups 6,7), loaded once per phase. tpre prefetch in
// poll shadow; CTA with no owned h exits immediately.
// ---------------------------------------------------------------------------
__global__ __launch_bounds__(1024, 1) void k_main(
    const int*   __restrict__ x,      const int*   __restrict__ target,
    const float* __restrict__ eps,
    const float* __restrict__ mu_W,    const float* __restrict__ mu_b,
    const float* __restrict__ lv_W,    const float* __restrict__ lv_b,
    float* __restrict__ out)
{
    extern __shared__ __align__(16) unsigned s_dyn[];
    unsigned* s_w     = s_dyn + OFF_W;               // [54][1024] u32 (2 u16)
    float*    s_h     = (float*)(s_dyn + OFF_H);     // [2048]
    float*    s_part  = (float*)(s_dyn + OFF_PART);  // [56][4]

    const int tid = threadIdx.x, lane = tid & 31, w = tid >> 5;
    const int g = w >> 2;        // row-group 0..7
    const int q = w & 3;         // k-slice 0..3
    const int j0 = blockIdx.x * CPB;
    int nloc = H - j0;
    if (nloc > CPB) nloc = CPB;
    if (nloc <= 0) return;       // CTA 147 owns nothing; exit (publishes none)
    const int nrows = nloc * 4;
    const bool full = (nloc == CPB);

    float cacc = 0.0f;                       // LSTM cell state (owner threads)
    const unsigned base = g_base;            // set by k_pre this launch

    for (int phase = 0; phase < 2; phase++) {
        const unsigned short* Wq = g_Wq[phase];
        const float* wsc   = g_wscale[phase];
        const float* table = g_table + (size_t)phase * V * G4;

        // ---- load the 54 SMEM-resident weight rows for this phase ----
        __syncthreads();
        {
            const unsigned* Wq32 = reinterpret_cast<const unsigned*>(Wq);
            for (int g2 = 0; g2 < 8; g2++) {
                const int kc = (g2 < 6) ? 7 : 6;
                for (int k = 0; k < kc; k++) {
                    const int lr = g2 + 8 * k;
                    if (lr < nrows) {
                        const int sidx = (g2 < 6) ? (g2 * 7 + k)
                                                  : (42 + (g2 - 6) * 6 + k);
                        const int row = (lr & 3) * H + j0 + (lr >> 2);
                        s_w[sidx * 1024 + tid] =
                            __ldg(&Wq32[(size_t)row * 1024 + tid]);
                    }
                }
            }
        }
        __syncthreads();

        // rows 54/55 register-resident for groups 6,7 (constant per phase)
        const int lrs = 48 + g;
        const bool strm = (g >= 6) && (lrs < nrows);
        uint2 pfr[4];
        if (strm) {
            const int row = (lrs & 3) * H + j0 + (lrs >> 2);
            const uint2* gw = reinterpret_cast<const uint2*>(
                Wq + (size_t)row * H) + q * 128 + lane;
#pragma unroll
            for (int c = 0; c < 4; c++) pfr[c] = __ldg(&gw[c * 32]);
        }
        float wscR[4];                        // owner dequant scales (static)
        if (tid < nloc) {
#pragma unroll
            for (int ga = 0; ga < 4; ga++)
                wscR[ga] = __ldg(&wsc[ga * H + j0 + tid]);
        }

        for (int t = 0; t < T; t++) {
            const int sread = (phase == 0) ? t : (513 + t);
            const int rbuf  = sread & 3;
            const int wbuf  = (sread + 1) & 3;
            const unsigned want = base + (unsigned)sread;

            // owner: issue tok load before the poll (hidden by it)
            int tok = 0;
            if (tid < nloc)
                tok = (phase == 0) ? __ldg(&x[t])
                                   : (t == 0 ? 0 : __ldg(&target[t - 1]));

            // self-flagged h: poll this thread's two elements, drop into smem
            reinterpret_cast<float2*>(s_h)[tid] =
                poll_h2(&g_hd[rbuf][2 * tid], want);

            // owner: table prefetch issued in the bar shadow
            float tpre[4];
            if (tid < nloc) {
#pragma unroll
                for (int ga = 0; ga < 4; ga++)
                    tpre[ga] = __ldg(&table[(size_t)tok * G4 + ga * H + j0 + tid]);
            }
            __syncthreads();

            // per-warp h-slice, packed f32x2: k = q*512 + c*128 + lane*4
            const float4* sh4 = reinterpret_cast<const float4*>(s_h);
            unsigned long long hp[8];
            float hsum = 0.0f;
#pragma unroll
            for (int c = 0; c < 4; c++) {
                float4 hv = sh4[q * 128 + c * 32 + lane];
                hp[2 * c]     = pkf(hv.x, hv.y);
                hp[2 * c + 1] = pkf(hv.z, hv.w);
                hsum += (hv.x + hv.y) + (hv.z + hv.w);
            }

            if (full) {
                if (g < 6) {
                    const uint2* wbase = reinterpret_cast<const uint2*>(s_w) +
                                         (size_t)(g * 7) * 512 + q * 128 + lane;
#pragma unroll
                    for (int k = 0; k < 7; k++) {
                        const uint2* wp = wbase + (size_t)k * 512;
                        uint2 w0 = wp[0], w1 = wp[32], w2 = wp[64], w3 = wp[96];
                        ROW_DOT2(w0, w1, w2, w3, accr)
                        float s = warpsum(accr);
                        if (lane == 0) s_part[(g + 8 * k) * 4 + q] = s;
                    }
                } else {
                    const uint2* wbase = reinterpret_cast<const uint2*>(s_w) +
                                         (size_t)(42 + (g - 6) * 6) * 512 +
                                         q * 128 + lane;
#pragma unroll
                    for (int k = 0; k < 6; k++) {
                        const uint2* wp = wbase + (size_t)k * 512;
                        uint2 w0 = wp[0], w1 = wp[32], w2 = wp[64], w3 = wp[96];
                        ROW_DOT2(w0, w1, w2, w3, accr)
                        float s = warpsum(accr);
                        if (lane == 0) s_part[(g + 8 * k) * 4 + q] = s;
                    }
                    ROW_DOT2(pfr[0], pfr[1], pfr[2], pfr[3], accr)
                    float s = warpsum(accr);
                    if (lane == 0) s_part[(48 + g) * 4 + q] = s;
                }
            } else {
                // ---- slow path (tail CTA): guarded loops ----
                const int kc = (g < 6) ? 7 : 6;
                for (int k = 0; k < kc; k++) {
                    const int lr = g + 8 * k;
                    if (lr < nrows) {
                        const int sidx = (g < 6) ? (g * 7 + k)
                                                 : (42 + (g - 6) * 6 + k);
                        const uint2* wp = reinterpret_cast<const uint2*>(s_w) +
                                          (size_t)sidx * 512 + q * 128 + lane;
                        uint2 w0 = wp[0], w1 = wp[32], w2 = wp[64], w3 = wp[96];
                        ROW_DOT2(w0, w1, w2, w3, accr)
                        float s = warpsum(accr);
                        if (lane == 0) s_part[lr * 4 + q] = s;
                    }
                }
                if (strm) {
                    ROW_DOT2(pfr[0], pfr[1], pfr[2], pfr[3], accr)
                    float s = warpsum(accr);
                    if (lane == 0) s_part[lrs * 4 + q] = s;
                }
            }
            __syncthreads();

            // fused combine + dequant + table + cell update (owner threads)
            if (tid < nloc) {
                const float4* sp4 = reinterpret_cast<const float4*>(s_part);
                float4 p0 = sp4[tid * 4 + 0];
                float4 p1 = sp4[tid * 4 + 1];
                float4 p2 = sp4[tid * 4 + 2];
                float4 p3 = sp4[tid * 4 + 3];
                float g0 = ((p0.x + p0.y) + (p0.z + p0.w)) * wscR[0] + tpre[0];
                float g1 = ((p1.x + p1.y) + (p1.z + p1.w)) * wscR[1] + tpre[1];
                float g2 = ((p2.x + p2.y) + (p2.z + p2.w)) * wscR[2] + tpre[2];
                float g3 = ((p3.x + p3.y) + (p3.z + p3.w)) * wscR[3] + tpre[3];
                float c = sigm(g1) * cacc + sigm(g0) * tanhf(g2);
                cacc = c;
                float h = sigm(g3) * tanhf(c);
                publish_h(&g_hd[wbuf][j0 + tid], h, want + 1u);
                if (phase)
                    out[512 + (size_t)t * H + j0 + tid] = h;
            }
            // no grid barrier
        }

        if (phase == 0) {
            // VAE heads: s=512. read h_enc (buf 0, stamp base+512),
            // write z -> buf 1, stamp base+513.
            const unsigned want = base + 512u;
            reinterpret_cast<float2*>(s_h)[tid] =
                poll_h2(&g_hd[0][2 * tid], want);
            __syncthreads();
            const float4* sh4 = reinterpret_cast<const float4*>(s_h);
            if (w < nloc * 2) {
                const int l = w >> 1, m = w & 1;
                const float* Wm = m ? lv_W : mu_W;
                const int row = j0 + l;
                const float4* W4 = reinterpret_cast<const float4*>(Wm) +
                                   (size_t)row * (H / 4);
                float s = 0.0f;
#pragma unroll 8
                for (int i = lane; i < H / 4; i += 32) {
                    float4 a = __ldg(&W4[i]);
                    float4 b = sh4[i];
                    s += a.x * b.x + a.y * b.y + a.z * b.z + a.w * b.w;
                }
                s = warpsum(s);
                if (lane == 0)
                    s_part[w] = s + __ldg(&(m ? lv_b : mu_b)[row]);
            }
            __syncthreads();
            if (tid < nloc) {
                const int j = j0 + tid;
                const float mu = s_part[tid * 2 + 0];
                const float lv = s_part[tid * 2 + 1];
                out[512 + (size_t)T * H + j]     = mu;
                out[512 + (size_t)T * H + H + j] = lv;
                float z = mu + __ldg(&eps[j]) * expf(0.5f * lv);
                publish_h(&g_hd[1][j], z, want + 1u);
            }
        }
    }
}

// ---------------------------------------------------------------------------
// Argmax over hidden dim of each decoder output row (first-index tie-break).
// ---------------------------------------------------------------------------
__global__ __launch_bounds__(256) void k_argmax(float* __restrict__ out)
{
    __shared__ float sv[256];
    __shared__ int   si[256];
    const int t = blockIdx.x;
    const float* row = out + 512 + (size_t)t * H;
    float best = -3.402823466e+38f;
    int   bi = 0;
    for (int j = threadIdx.x; j < H; j += 256) {
        float v = row[j];
        if (v > best) { best = v; bi = j; }
    }
    sv[threadIdx.x] = best;
    si[threadIdx.x] = bi;
    __syncthreads();
    for (int s = 128; s; s >>= 1) {
        if (threadIdx.x < s) {
            float ov = sv[threadIdx.x + s];
            int   oi = si[threadIdx.x + s];
            if (ov > sv[threadIdx.x] ||
                (ov == sv[threadIdx.x] && oi < si[threadIdx.x])) {
                sv[threadIdx.x] = ov;
                si[threadIdx.x] = oi;
            }
        }
        __syncthreads();
    }
    if (threadIdx.x == 0) out[t] = (float)si[0];
}

// ---------------------------------------------------------------------------
extern "C" void kernel_launch(void* const* d_in, const int* in_sizes, int n_in,
                              void* d_out, int out_size)
{
    const int*   x       = (const int*)  d_in[0];
    const int*   target  = (const int*)  d_in[1];
    const float* eps     = (const float*)d_in[2];
    const float* enc_emb = (const float*)d_in[3];
    const float* enc_Wih = (const float*)d_in[4];
    const float* enc_Whh = (const float*)d_in[5];
    const float* enc_bih = (const float*)d_in[6];
    const float* enc_bhh = (const float*)d_in[7];
    const float* mu_W    = (const float*)d_in[8];
    const float* mu_b    = (const float*)d_in[9];
    const float* lv_W    = (const float*)d_in[10];
    const float* lv_b    = (const float*)d_in[11];
    const float* dec_emb = (const float*)d_in[12];
    const float* dec_Wih = (const float*)d_in[13];
    const float* dec_Whh = (const float*)d_in[14];
    const float* dec_bih = (const float*)d_in[15];
    const float* dec_bhh = (const float*)d_in[16];
    float* out = (float*)d_out;

    cudaFuncSetAttribute(k_main, cudaFuncAttributeMaxDynamicSharedMemorySize,
                         SMEM_BYTES);

    k_pre<<<1024, 256>>>(enc_emb, enc_Wih, enc_bih, enc_bhh,
                         dec_emb, dec_Wih, dec_bih, dec_bhh);
    k_quant<<<2 * G4, 256>>>(enc_Whh, dec_Whh);
    k_main<<<NCTA, 1024, SMEM_BYTES>>>(x, target, eps,
                                       mu_W, mu_b, lv_W, lv_b, out);
    k_argmax<<<512, 256>>>(out);
}

// round 17
// speedup vs baseline: 1.1215x; 1.0518x over previous
#include <cuda_runtime.h>
#include <cuda_bf16.h>

#define H     2048
#define G4    8192          // 4*H gate rows
#define V     28
#define T     512
#define NCTA  148
#define CPB   14            // h-indices per CTA
#define ROWS  56            // gate rows per CTA
#define SMEM_ROWS 54        // rows resident in SMEM; rows 54,55 in registers
#define WMAT  16777216      // G4*H elements per matrix
#define KMAGIC 8421376.0f   // 2^23 + 32768 (biased-u16 float offset)
#define EPOCH 2048u         // stamp-space advance per launch (>= 1026 used)

// dynamic smem layout (u32 units)
#define OFF_W     0
#define OFF_H     (SMEM_ROWS * 1024)            // 55296
#define OFF_PART  (OFF_H + 2048)                // 57344  : 56 rows x 4 slices
#define SMEM_U32  (OFF_PART + ROWS * 4)         // 57568
#define SMEM_BYTES (SMEM_U32 * 4)               // 230272 (<= 227KB opt-in)

// ---- device scratch (no allocations allowed) ----
__device__ float          g_table[2u * V * G4]; // [enc/dec][vocab][4H] gate table
__device__ unsigned short g_Wq[2][WMAT];        // biased-u16 quantized Whh
__device__ float          g_wscale[2][G4];      // per-row dequant scales
// hidden state, 4-deep ring, SELF-FLAGGED: low32 = value bits, high32 = stamp.
__device__ __align__(16) unsigned long long g_hd[4][H];
__device__ unsigned       g_base;               // stamp epoch (+=EPOCH per launch)

__device__ __forceinline__ float warpsum(float v) {
#pragma unroll
    for (int o = 16; o; o >>= 1) v += __shfl_xor_sync(0xffffffffu, v, o);
    return v;
}

// HW tanh (sm_75+): single-instruction approximation, abs err ~1e-5.
__device__ __forceinline__ float tanh_fast(float x) {
    float r;
    asm("tanh.approx.f32 %0, %1;" : "=f"(r) : "f"(x));
    return r;
}
__device__ __forceinline__ float sigm_fast(float x) {
    return fmaf(0.5f, tanh_fast(0.5f * x), 0.5f);
}

// Publish one (value,stamp) word: strong release store.
__device__ __forceinline__ void publish_h(unsigned long long* dst, float v,
                                          unsigned stamp) {
    unsigned long long pk =
        ((unsigned long long)stamp << 32) | (unsigned long long)__float_as_uint(v);
    asm volatile("st.release.gpu.global.b64 [%0], %1;"
                 :: "l"(dst), "l"(pk) : "memory");
}

// Poll: dual acquire-load spin (both loads independent -> in flight together).
__device__ __forceinline__ float2 poll_h2(const unsigned long long* src,
                                          unsigned want) {
    unsigned long long v0, v1;
    for (;;) {
        asm volatile("ld.acquire.gpu.global.b64 %0, [%1];"
                     : "=l"(v0) : "l"(src) : "memory");
        asm volatile("ld.acquire.gpu.global.b64 %0, [%1];"
                     : "=l"(v1) : "l"(src + 1) : "memory");
        if ((unsigned)(v0 >> 32) == want && (unsigned)(v1 >> 32) == want) break;
    }
    return make_float2(__uint_as_float((unsigned)v0),
                       __uint_as_float((unsigned)v1));
}

// biased-u16 pair -> packed f32x2 (value = 2^23 + biased) via 2 PRMT + pair.
__device__ __forceinline__ unsigned long long pk2(unsigned u) {
    unsigned long long r;
    asm("{\n\t.reg .b32 lo, hi;\n\t"
        "prmt.b32 lo, %1, %2, 0x7410;\n\t"
        "prmt.b32 hi, %1, %2, 0x7432;\n\t"
        "mov.b64 %0, {lo, hi};\n\t}"
        : "=l"(r) : "r"(u), "r"(0x4B000000u));
    return r;
}
__device__ __forceinline__ void fma2(unsigned long long& a,
                                     unsigned long long wv,
                                     unsigned long long hv) {
    asm("fma.rn.f32x2 %0, %1, %2, %0;" : "+l"(a) : "l"(wv), "l"(hv));
}
__device__ __forceinline__ unsigned long long pkf(float lo, float hi) {
    unsigned long long r;
    asm("mov.b64 %0, {%1, %2};" : "=l"(r) : "f"(lo), "f"(hi));
    return r;
}
__device__ __forceinline__ float unpk_sum(unsigned long long a,
                                          unsigned long long b) {
    float x0, y0, x1, y1;
    asm("mov.b64 {%0, %1}, %2;" : "=f"(x0), "=f"(y0) : "l"(a));
    asm("mov.b64 {%0, %1}, %2;" : "=f"(x1), "=f"(y1) : "l"(b));
    return (x0 + y0) + (x1 + y1);
}

#define ROW_DOT2(w0, w1, w2, w3, OUTVAR)                                  \
    float OUTVAR;                                                         \
    {                                                                     \
        unsigned long long a0 = 0ull, a1 = 0ull;                          \
        fma2(a0, pk2(w0.x), hp[0]); fma2(a1, pk2(w0.y), hp[1]);           \
        fma2(a0, pk2(w1.x), hp[2]); fma2(a1, pk2(w1.y), hp[3]);           \
        fma2(a0, pk2(w2.x), hp[4]); fma2(a1, pk2(w2.y), hp[5]);           \
        fma2(a0, pk2(w3.x), hp[6]); fma2(a1, pk2(w3.y), hp[7]);           \
        OUTVAR = fmaf(-KMAGIC, hsum, unpk_sum(a0, a1));                   \
    }

// ---------------------------------------------------------------------------
// Fused prep kernel. Blocks 0..1023: per-vocab gate tables (2 rows/warp).
// Blocks 1024..17407: quantize Whh rows to biased uint16.
// Block 0 additionally advances the stamp epoch and publishes S(0)=0.
// Latency-bound table blocks overlap with DRAM-bound quant blocks.
// ---------------------------------------------------------------------------
__global__ __launch_bounds__(256) void k_prep(
    const float* __restrict__ enc_emb, const float* __restrict__ enc_Wih,
    const float* __restrict__ enc_bih, const float* __restrict__ enc_bhh,
    const float* __restrict__ dec_emb, const float* __restrict__ dec_Wih,
    const float* __restrict__ dec_bih, const float* __restrict__ dec_bhh,
    const float* __restrict__ encW,    const float* __restrict__ decW)
{
    __shared__ __align__(16) float s_emb[V][256];
    __shared__ unsigned s_base;
    __shared__ float s_max[8];
    const int tid = threadIdx.x, lane = tid & 31, warp = tid >> 5;

    if (blockIdx.x >= 1024) {
        // ---------------- quant part ----------------
        const int r     = blockIdx.x - 1024;   // 0..16383
        const int which = r >> 13;
        const int row   = r & (G4 - 1);

        const float4* W4 = reinterpret_cast<const float4*>(
            (which ? decW : encW) + (size_t)row * H);

        float4 v0 = __ldg(&W4[tid]);
        float4 v1 = __ldg(&W4[tid + 256]);

        float m = fmaxf(fmaxf(fabsf(v0.x), fabsf(v0.y)),
                        fmaxf(fabsf(v0.z), fabsf(v0.w)));
        m = fmaxf(m, fmaxf(fmaxf(fabsf(v1.x), fabsf(v1.y)),
                           fmaxf(fabsf(v1.z), fabsf(v1.w))));
#pragma unroll
        for (int o = 16; o; o >>= 1)
            m = fmaxf(m, __shfl_xor_sync(0xffffffffu, m, o));
        if (lane == 0) s_max[warp] = m;
        __syncthreads();
        if (tid == 0) {
            float mm = s_max[0];
#pragma unroll
            for (int i = 1; i < 8; i++) mm = fmaxf(mm, s_max[i]);
            s_max[0] = mm;
            g_wscale[which][row] = mm * (1.0f / 32766.0f);
        }
        __syncthreads();
        const float mv  = s_max[0];
        const float inv = (mv > 0.0f) ? (32766.0f / mv) : 0.0f;

        ushort4* Q4 = reinterpret_cast<ushort4*>(&g_Wq[which][(size_t)row * H]);
        ushort4 q;
        q.x = (unsigned short)(__float2int_rn(v0.x * inv) + 32768);
        q.y = (unsigned short)(__float2int_rn(v0.y * inv) + 32768);
        q.z = (unsigned short)(__float2int_rn(v0.z * inv) + 32768);
        q.w = (unsigned short)(__float2int_rn(v0.w * inv) + 32768);
        Q4[tid] = q;
        q.x = (unsigned short)(__float2int_rn(v1.x * inv) + 32768);
        q.y = (unsigned short)(__float2int_rn(v1.y * inv) + 32768);
        q.z = (unsigned short)(__float2int_rn(v1.z * inv) + 32768);
        q.w = (unsigned short)(__float2int_rn(v1.w * inv) + 32768);
        Q4[tid + 256] = q;
        return;
    }

    // ---------------- table part ----------------
    if (blockIdx.x == 0) {
        if (tid == 0) {
            unsigned nb = g_base + EPOCH;
            g_base = nb;
            s_base = nb;
        }
        __syncthreads();
        const unsigned nb = s_base;
        for (int j = tid; j < H; j += 256)
            publish_h(&g_hd[0][j], 0.0f, nb);
    }

    const int   which = (blockIdx.x >= 512) ? 1 : 0;
    const float* emb = which ? dec_emb : enc_emb;
    const float* Wih = which ? dec_Wih : enc_Wih;
    const float* bih = which ? dec_bih : enc_bih;
    const float* bhh = which ? dec_bhh : enc_bhh;
    const int row0 = (blockIdx.x & 511) * 16 + warp * 2;   // even row

    float acc0[V], acc1[V];
#pragma unroll
    for (int v = 0; v < V; v++) { acc0[v] = 0.0f; acc1[v] = 0.0f; }

    for (int kt = 0; kt < 8; kt++) {
        const int k0 = kt * 256;
        __syncthreads();
        for (int idx = tid; idx < V * 256; idx += 256) {
            int v = idx >> 8, kk = idx & 255;
            s_emb[v][kk] = __ldg(&emb[v * H + k0 + kk]);
        }
        __syncthreads();
        const float4* W0 = reinterpret_cast<const float4*>(
            Wih + (size_t)row0 * H + k0);
        const float4* W1 = reinterpret_cast<const float4*>(
            Wih + (size_t)(row0 + 1) * H + k0);
#pragma unroll
        for (int it = 0; it < 2; it++) {
            const int kl = it * 32 + lane;
            float4 a0 = __ldg(&W0[kl]);
            float4 a1 = __ldg(&W1[kl]);
#pragma unroll
            for (int v = 0; v < V; v++) {
                float4 e = reinterpret_cast<const float4*>(s_emb[v])[kl];
                acc0[v] += a0.x * e.x + a0.y * e.y + a0.z * e.z + a0.w * e.w;
                acc1[v] += a1.x * e.x + a1.y * e.y + a1.z * e.z + a1.w * e.w;
            }
        }
    }

    float b0 = 0.0f, b1 = 0.0f;
#pragma unroll
    for (int v = 0; v < V; v++) {
        float s0 = warpsum(acc0[v]);
        float s1 = warpsum(acc1[v]);
        if (lane == 0) {
            if (v == 0) {
                b0 = __ldg(&bih[row0]) + __ldg(&bhh[row0]);
                b1 = __ldg(&bih[row0 + 1]) + __ldg(&bhh[row0 + 1]);
            }
            g_table[(size_t)which * V * G4 + (size_t)v * G4 + row0]     = s0 + b0;
            g_table[(size_t)which * V * G4 + (size_t)v * G4 + row0 + 1] = s1 + b1;
        }
    }
}

// ---------------------------------------------------------------------------
// Persistent LSTM kernel. 148 CTAs x 1024 threads. Identical to round 16
// except activations use HW tanh.approx (sigm via tanh identity).
// ---------------------------------------------------------------------------
__global__ __launch_bounds__(1024, 1) void k_main(
    const int*   __restrict__ x,      const int*   __restrict__ target,
    const float* __restrict__ eps,
    const float* __restrict__ mu_W,    const float* __restrict__ mu_b,
    const float* __restrict__ lv_W,    const float* __restrict__ lv_b,
    float* __restrict__ out)
{
    extern __shared__ __align__(16) unsigned s_dyn[];
    unsigned* s_w     = s_dyn + OFF_W;               // [54][1024] u32 (2 u16)
    float*    s_h     = (float*)(s_dyn + OFF_H);     // [2048]
    float*    s_part  = (float*)(s_dyn + OFF_PART);  // [56][4]

    const int tid = threadIdx.x, lane = tid & 31, w = tid >> 5;
    const int g = w >> 2;        // row-group 0..7
    const int q = w & 3;         // k-slice 0..3
    const int j0 = blockIdx.x * CPB;
    int nloc = H - j0;
    if (nloc > CPB) nloc = CPB;
    if (nloc <= 0) return;       // CTA 147 owns nothing; exit
    const int nrows = nloc * 4;
    const bool full = (nloc == CPB);

    float cacc = 0.0f;                       // LSTM cell state (owner threads)
    const unsigned base = g_base;            // set by k_prep this launch

    for (int phase = 0; phase < 2; phase++) {
        const unsigned short* Wq = g_Wq[phase];
        const float* wsc   = g_wscale[phase];
        const float* table = g_table + (size_t)phase * V * G4;

        // ---- load the 54 SMEM-resident weight rows for this phase ----
        __syncthreads();
        {
            const unsigned* Wq32 = reinterpret_cast<const unsigned*>(Wq);
            for (int g2 = 0; g2 < 8; g2++) {
                const int kc = (g2 < 6) ? 7 : 6;
                for (int k = 0; k < kc; k++) {
                    const int lr = g2 + 8 * k;
                    if (lr < nrows) {
                        const int sidx = (g2 < 6) ? (g2 * 7 + k)
                                                  : (42 + (g2 - 6) * 6 + k);
                        const int row = (lr & 3) * H + j0 + (lr >> 2);
                        s_w[sidx * 1024 + tid] =
                            __ldg(&Wq32[(size_t)row * 1024 + tid]);
                    }
                }
            }
        }
        __syncthreads();

        // rows 54/55 register-resident for groups 6,7 (constant per phase)
        const int lrs = 48 + g;
        const bool strm = (g >= 6) && (lrs < nrows);
        uint2 pfr[4];
        if (strm) {
            const int row = (lrs & 3) * H + j0 + (lrs >> 2);
            const uint2* gw = reinterpret_cast<const uint2*>(
                Wq + (size_t)row * H) + q * 128 + lane;
#pragma unroll
            for (int c = 0; c < 4; c++) pfr[c] = __ldg(&gw[c * 32]);
        }
        float wscR[4];                        // owner dequant scales (static)
        if (tid < nloc) {
#pragma unroll
            for (int ga = 0; ga < 4; ga++)
                wscR[ga] = __ldg(&wsc[ga * H + j0 + tid]);
        }

        for (int t = 0; t < T; t++) {
            const int sread = (phase == 0) ? t : (513 + t);
            const int rbuf  = sread & 3;
            const int wbuf  = (sread + 1) & 3;
            const unsigned want = base + (unsigned)sread;

            // owner: issue tok load before the poll (hidden by it)
            int tok = 0;
            if (tid < nloc)
                tok = (phase == 0) ? __ldg(&x[t])
                                   : (t == 0 ? 0 : __ldg(&target[t - 1]));

            // self-flagged h: poll this thread's two elements, drop into smem
            reinterpret_cast<float2*>(s_h)[tid] =
                poll_h2(&g_hd[rbuf][2 * tid], want);

            // owner: table prefetch issued in the bar shadow
            float tpre[4];
            if (tid < nloc) {
#pragma unroll
                for (int ga = 0; ga < 4; ga++)
                    tpre[ga] = __ldg(&table[(size_t)tok * G4 + ga * H + j0 + tid]);
            }
            __syncthreads();

            // per-warp h-slice, packed f32x2: k = q*512 + c*128 + lane*4
            const float4* sh4 = reinterpret_cast<const float4*>(s_h);
            unsigned long long hp[8];
            float hsum = 0.0f;
#pragma unroll
            for (int c = 0; c < 4; c++) {
                float4 hv = sh4[q * 128 + c * 32 + lane];
                hp[2 * c]     = pkf(hv.x, hv.y);
                hp[2 * c + 1] = pkf(hv.z, hv.w);
                hsum += (hv.x + hv.y) + (hv.z + hv.w);
            }

            if (full) {
                if (g < 6) {
                    const uint2* wbase = reinterpret_cast<const uint2*>(s_w) +
                                         (size_t)(g * 7) * 512 + q * 128 + lane;
#pragma unroll
                    for (int k = 0; k < 7; k++) {
                        const uint2* wp = wbase + (size_t)k * 512;
                        uint2 w0 = wp[0], w1 = wp[32], w2 = wp[64], w3 = wp[96];
                        ROW_DOT2(w0, w1, w2, w3, accr)
                        float s = warpsum(accr);
                        if (lane == 0) s_part[(g + 8 * k) * 4 + q] = s;
                    }
                } else {
                    const uint2* wbase = reinterpret_cast<const uint2*>(s_w) +
                                         (size_t)(42 + (g - 6) * 6) * 512 +
                                         q * 128 + lane;
#pragma unroll
                    for (int k = 0; k < 6; k++) {
                        const uint2* wp = wbase + (size_t)k * 512;
                        uint2 w0 = wp[0], w1 = wp[32], w2 = wp[64], w3 = wp[96];
                        ROW_DOT2(w0, w1, w2, w3, accr)
                        float s = warpsum(accr);
                        if (lane == 0) s_part[(g + 8 * k) * 4 + q] = s;
                    }
                    ROW_DOT2(pfr[0], pfr[1], pfr[2], pfr[3], accr)
                    float s = warpsum(accr);
                    if (lane == 0) s_part[(48 + g) * 4 + q] = s;
                }
            } else {
                // ---- slow path (tail CTA): guarded loops ----
                const int kc = (g < 6) ? 7 : 6;
                for (int k = 0; k < kc; k++) {
                    const int lr = g + 8 * k;
                    if (lr < nrows) {
                        const int sidx = (g < 6) ? (g * 7 + k)
                                                 : (42 + (g - 6) * 6 + k);
                        const uint2* wp = reinterpret_cast<const uint2*>(s_w) +
                                          (size_t)sidx * 512 + q * 128 + lane;
                        uint2 w0 = wp[0], w1 = wp[32], w2 = wp[64], w3 = wp[96];
                        ROW_DOT2(w0, w1, w2, w3, accr)
                        float s = warpsum(accr);
                        if (lane == 0) s_part[lr * 4 + q] = s;
                    }
                }
                if (strm) {
                    ROW_DOT2(pfr[0], pfr[1], pfr[2], pfr[3], accr)
                    float s = warpsum(accr);
                    if (lane == 0) s_part[lrs * 4 + q] = s;
                }
            }
            __syncthreads();

            // fused combine + dequant + table + cell update (owner threads)
            if (tid < nloc) {
                const float4* sp4 = reinterpret_cast<const float4*>(s_part);
                float4 p0 = sp4[tid * 4 + 0];
                float4 p1 = sp4[tid * 4 + 1];
                float4 p2 = sp4[tid * 4 + 2];
                float4 p3 = sp4[tid * 4 + 3];
                float g0 = ((p0.x + p0.y) + (p0.z + p0.w)) * wscR[0] + tpre[0];
                float g1 = ((p1.x + p1.y) + (p1.z + p1.w)) * wscR[1] + tpre[1];
                float g2 = ((p2.x + p2.y) + (p2.z + p2.w)) * wscR[2] + tpre[2];
                float g3 = ((p3.x + p3.y) + (p3.z + p3.w)) * wscR[3] + tpre[3];
                float c = sigm_fast(g1) * cacc + sigm_fast(g0) * tanh_fast(g2);
                cacc = c;
                float h = sigm_fast(g3) * tanh_fast(c);
                publish_h(&g_hd[wbuf][j0 + tid], h, want + 1u);
                if (phase)
                    out[512 + (size_t)t * H + j0 + tid] = h;
            }
            // no grid barrier
        }

        if (phase == 0) {
            // VAE heads: s=512. read h_enc (buf 0, stamp base+512),
            // write z -> buf 1, stamp base+513.
            const unsigned want = base + 512u;
            reinterpret_cast<float2*>(s_h)[tid] =
                poll_h2(&g_hd[0][2 * tid], want);
            __syncthreads();
            const float4* sh4 = reinterpret_cast<const float4*>(s_h);
            if (w < nloc * 2) {
                const int l = w >> 1, m = w & 1;
                const float* Wm = m ? lv_W : mu_W;
                const int row = j0 + l;
                const float4* W4 = reinterpret_cast<const float4*>(Wm) +
                                   (size_t)row * (H / 4);
                float s = 0.0f;
#pragma unroll 8
                for (int i = lane; i < H / 4; i += 32) {
                    float4 a = __ldg(&W4[i]);
                    float4 b = sh4[i];
                    s += a.x * b.x + a.y * b.y + a.z * b.z + a.w * b.w;
                }
                s = warpsum(s);
                if (lane == 0)
                    s_part[w] = s + __ldg(&(m ? lv_b : mu_b)[row]);
            }
            __syncthreads();
            if (tid < nloc) {
                const int j = j0 + tid;
                const float mu = s_part[tid * 2 + 0];
                const float lv = s_part[tid * 2 + 1];
                out[512 + (size_t)T * H + j]     = mu;
                out[512 + (size_t)T * H + H + j] = lv;
                float z = mu + __ldg(&eps[j]) * expf(0.5f * lv);  // precise
                publish_h(&g_hd[1][j], z, want + 1u);
            }
        }
    }
}

// ---------------------------------------------------------------------------
// Argmax over hidden dim of each decoder output row (first-index tie-break).
// ---------------------------------------------------------------------------
__global__ __launch_bounds__(256) void k_argmax(float* __restrict__ out)
{
    __shared__ float sv[256];
    __shared__ int   si[256];
    const int t = blockIdx.x;
    const float* row = out + 512 + (size_t)t * H;
    float best = -3.402823466e+38f;
    int   bi = 0;
    for (int j = threadIdx.x; j < H; j += 256) {
        float v = row[j];
        if (v > best) { best = v; bi = j; }
    }
    sv[threadIdx.x] = best;
    si[threadIdx.x] = bi;
    __syncthreads();
    for (int s = 128; s; s >>= 1) {
        if (threadIdx.x < s) {
            float ov = sv[threadIdx.x + s];
            int   oi = si[threadIdx.x + s];
            if (ov > sv[threadIdx.x] ||
                (ov == sv[threadIdx.x] && oi < si[threadIdx.x])) {
                sv[threadIdx.x] = ov;
                si[threadIdx.x] = oi;
            }
        }
        __syncthreads();
    }
    if (threadIdx.x == 0) out[t] = (float)si[0];
}

// ---------------------------------------------------------------------------
extern "C" void kernel_launch(void* const* d_in, const int* in_sizes, int n_in,
                              void* d_out, int out_size)
{
    const int*   x       = (const int*)  d_in[0];
    const int*   target  = (const int*)  d_in[1];
    const float* eps     = (const float*)d_in[2];
    const float* enc_emb = (const float*)d_in[3];
    const float* enc_Wih = (const float*)d_in[4];
    const float* enc_Whh = (const float*)d_in[5];
    const float* enc_bih = (const float*)d_in[6];
    const float* enc_bhh = (const float*)d_in[7];
    const float* mu_W    = (const float*)d_in[8];
    const float* mu_b    = (const float*)d_in[9];
    const float* lv_W    = (const float*)d_in[10];
    const float* lv_b    = (const float*)d_in[11];
    const float* dec_emb = (const float*)d_in[12];
    const float* dec_Wih = (const float*)d_in[13];
    const float* dec_Whh = (const float*)d_in[14];
    const float* dec_bih = (const float*)d_in[15];
    const float* dec_bhh = (const float*)d_in[16];
    float* out = (float*)d_out;

    cudaFuncSetAttribute(k_main, cudaFuncAttributeMaxDynamicSharedMemorySize,
                         SMEM_BYTES);

    k_prep<<<1024 + 2 * G4, 256>>>(enc_emb, enc_Wih, enc_bih, enc_bhh,
                                   dec_emb, dec_Wih, dec_bih, dec_bhh,
                                   enc_Whh, dec_Whh);
    k_main<<<NCTA, 1024, SMEM_BYTES>>>(x, target, eps,
                                       mu_W, mu_b, lv_W, lv_b, out);
    k_argmax<<<512, 256>>>(out);
}